// round 2
// baseline (speedup 1.0000x reference)
#include <cuda_runtime.h>
#include <cstdint>

#define CDIM 64
#define MAXN 20000
#define AGGW 576   // 64 + 64*3 + 64*5

// Scratch: __device__ globals (no allocation allowed anywhere).
// __align__(16) is load-bearing: red.global.add.v4.f32 requires 16B-aligned addresses.
__device__ __align__(16) float g_h[MAXN * CDIM];       // up-projected node feats, 5 MB
__device__ __align__(16) float g_agg[MAXN * AGGW];     // scatter accumulator, 46 MB (L2-resident)

__device__ __forceinline__ float silu_f(float x) {
    return x / (1.0f + __expf(-x));
}

__device__ __forceinline__ void red_add_v4(float* addr, float a, float b, float c, float d) {
    asm volatile("red.global.add.v4.f32 [%0], {%1,%2,%3,%4};"
                 :: "l"(addr), "f"(a), "f"(b), "f"(c), "f"(d) : "memory");
}

// ---------------------------------------------------------------- zero agg
__global__ void zero_agg_kernel(int n4) {
    float4 z = make_float4(0.f, 0.f, 0.f, 0.f);
    float4* p = reinterpret_cast<float4*>(g_agg);
    for (int i = blockIdx.x * blockDim.x + threadIdx.x; i < n4; i += gridDim.x * blockDim.x)
        p[i] = z;
}

// ---------------------------------------------------------------- h = nf @ w_up * 1/8
__global__ __launch_bounds__(256) void h_kernel(const float* __restrict__ nf,
                                                const float* __restrict__ wup, int Nn) {
    __shared__ float Ws[4096];
    __shared__ float nfs[256];
    int tid = threadIdx.x;
    for (int i = tid; i < 1024; i += 256)
        reinterpret_cast<float4*>(Ws)[i] = reinterpret_cast<const float4*>(wup)[i];
    int n0 = blockIdx.x * 4;
    int nl = tid >> 6, j = tid & 63;
    int n = n0 + nl;
    nfs[tid] = (n < Nn) ? nf[(size_t)n * 64 + j] : 0.f;
    __syncthreads();
    float acc = 0.f;
#pragma unroll 8
    for (int c = 0; c < 64; c++) acc += nfs[nl * 64 + c] * Ws[c * 64 + j];
    if (n < Nn) g_h[(size_t)n * 64 + j] = acc * 0.125f;
}

// ---------------------------------------------------------------- 64x64 register-tiled GEMM
// C[e][j] = act( sc * sum_k A[e][k] * B[k*ldb + j] ),  A/C are [64][64] smem, 256 threads.
template <bool DOSILU>
__device__ __forceinline__ void gemm64(const float* __restrict__ A,
                                       const float* __restrict__ B, int ldb,
                                       float* __restrict__ Cc, float sc) {
    int tx = threadIdx.x & 15;   // output col group (j = tx*4 .. +3)
    int ty = threadIdx.x >> 4;   // output row group (e = ty*4 .. +3)
    float acc[4][4];
#pragma unroll
    for (int i = 0; i < 4; i++)
#pragma unroll
        for (int j = 0; j < 4; j++) acc[i][j] = 0.f;
    const float* Bp = B + tx * 4;
    const float* Ap = A + ty * 4 * 64;
#pragma unroll 4
    for (int k = 0; k < 64; k++) {
        float4 b = *reinterpret_cast<const float4*>(Bp + k * ldb);
        float a0 = Ap[k];
        float a1 = Ap[64 + k];
        float a2 = Ap[128 + k];
        float a3 = Ap[192 + k];
        acc[0][0] += a0 * b.x; acc[0][1] += a0 * b.y; acc[0][2] += a0 * b.z; acc[0][3] += a0 * b.w;
        acc[1][0] += a1 * b.x; acc[1][1] += a1 * b.y; acc[1][2] += a1 * b.z; acc[1][3] += a1 * b.w;
        acc[2][0] += a2 * b.x; acc[2][1] += a2 * b.y; acc[2][2] += a2 * b.z; acc[2][3] += a2 * b.w;
        acc[3][0] += a3 * b.x; acc[3][1] += a3 * b.y; acc[3][2] += a3 * b.z; acc[3][3] += a3 * b.w;
    }
#pragma unroll
    for (int i = 0; i < 4; i++) {
        float4 o;
        o.x = acc[i][0] * sc; o.y = acc[i][1] * sc; o.z = acc[i][2] * sc; o.w = acc[i][3] * sc;
        if (DOSILU) { o.x = silu_f(o.x); o.y = silu_f(o.y); o.z = silu_f(o.z); o.w = silu_f(o.w); }
        *reinterpret_cast<float4*>(Cc + (ty * 4 + i) * 64 + tx * 4) = o;
    }
}

// ---------------------------------------------------------------- fused edge kernel
// Per 64-edge tile: radial MLP (8->64->64->64->192), spherical harmonics,
// sender gather, factorized message scatter (v4 reductions into g_agg).
__global__ __launch_bounds__(256, 1) void edge_kernel(
    const float* __restrict__ vectors, const float* __restrict__ radial,
    const int* __restrict__ senders, const int* __restrict__ receivers,
    const float* __restrict__ w1, const float* __restrict__ w2,
    const float* __restrict__ w3, const float* __restrict__ w4, int E) {
    extern __shared__ float sm[];
    float* W1   = sm;              // 512
    float* W2   = W1 + 512;        // 4096
    float* W3   = W2 + 4096;       // 4096
    float* W4   = W3 + 4096;       // 12288
    float* bufA = W4 + 12288;      // 4096
    float* bufB = bufA + 4096;     // 4096
    float* Ss   = bufB + 4096;     // 4096  gathered sender feats
    float* Gs   = Ss + 4096;       // 512   radial
    float* Ys   = Gs + 512;        // 512   y1(3)+y2(5) per edge
    int*   Sn   = reinterpret_cast<int*>(Ys + 512);  // 64
    int*   Rc   = Sn + 64;                           // 64

    const int tid = threadIdx.x;
    const int e0 = blockIdx.x * 64;

    // cooperative weight load (L2-resident)
    for (int i = tid; i < 128;  i += 256) reinterpret_cast<float4*>(W1)[i] = reinterpret_cast<const float4*>(w1)[i];
    for (int i = tid; i < 1024; i += 256) reinterpret_cast<float4*>(W2)[i] = reinterpret_cast<const float4*>(w2)[i];
    for (int i = tid; i < 1024; i += 256) reinterpret_cast<float4*>(W3)[i] = reinterpret_cast<const float4*>(w3)[i];
    for (int i = tid; i < 3072; i += 256) reinterpret_cast<float4*>(W4)[i] = reinterpret_cast<const float4*>(w4)[i];

    // radial embedding
    for (int i = tid; i < 512; i += 256) {
        int e = e0 + (i >> 3);
        Gs[i] = (e < E) ? radial[(size_t)e * 8 + (i & 7)] : 0.f;
    }
    // per-edge: ids + spherical harmonics
    if (tid < 64) {
        int e = e0 + tid;
        int s = 0, r = 0;
        float vx = 1.f, vy = 0.f, vz = 0.f;
        if (e < E) {
            s = senders[e]; r = receivers[e];
            vx = vectors[(size_t)e * 3 + 0];
            vy = vectors[(size_t)e * 3 + 1];
            vz = vectors[(size_t)e * 3 + 2];
        }
        Sn[tid] = s; Rc[tid] = r;
        float rn = rsqrtf(vx * vx + vy * vy + vz * vz);
        float x = vx * rn, y = vy * rn, z = vz * rn;
        const float s3  = 1.7320508075688772f;   // sqrt(3)
        const float s15 = 3.872983346207417f;    // sqrt(15)
        const float s5h = 1.118033988749895f;    // 0.5*sqrt(5)
        Ys[tid * 8 + 0] = s3 * x;
        Ys[tid * 8 + 1] = s3 * y;
        Ys[tid * 8 + 2] = s3 * z;
        Ys[tid * 8 + 3] = s15 * x * y;
        Ys[tid * 8 + 4] = s15 * y * z;
        Ys[tid * 8 + 5] = s5h * (3.f * z * z - 1.f);
        Ys[tid * 8 + 6] = s15 * x * z;
        Ys[tid * 8 + 7] = 0.5f * s15 * (x * x - y * y);
    }
    __syncthreads();

    // gather sender up-projected feats (h fits in L2)
    for (int i = tid; i < 4096; i += 256)
        Ss[i] = g_h[(size_t)Sn[i >> 6] * 64 + (i & 63)];

    // MLP layer 1: 8 -> 64
    for (int i = tid; i < 4096; i += 256) {
        int e = i >> 6, k = i & 63;
        float acc = 0.f;
#pragma unroll
        for (int r8 = 0; r8 < 8; r8++) acc += Gs[e * 8 + r8] * W1[r8 * 64 + k];
        bufA[i] = silu_f(acc * 0.35355339059327373f);  // 1/sqrt(8)
    }
    __syncthreads();
    gemm64<true>(bufA, W2, 64, bufB, 0.125f);
    __syncthreads();
    gemm64<true>(bufB, W3, 64, bufA, 0.125f);  // H3 in bufA
    __syncthreads();

    const float SC = 1.0f / 64.0f;

    // ---- l = 0 : mix chunk + scatter (16 v4 per edge)
    gemm64<false>(bufA, W4, 192, bufB, 0.125f);
    __syncthreads();
    for (int q = tid; q < 1024; q += 256) {
        int e = q >> 4, c4 = (q & 15) << 2;
        if (e0 + e < E) {
            const float* mp = bufB + e * 64 + c4;
            const float* sp = Ss + e * 64 + c4;
            red_add_v4(&g_agg[(size_t)Rc[e] * AGGW + c4],
                       mp[0] * sp[0] * SC, mp[1] * sp[1] * SC,
                       mp[2] * sp[2] * SC, mp[3] * sp[3] * SC);
        }
    }
    __syncthreads();

    // ---- l = 1 : (c,3) block, 48 v4 per edge
    gemm64<false>(bufA, W4 + 64, 192, bufB, 0.125f);
    __syncthreads();
    for (int q = tid; q < 3072; q += 256) {
        int e = q / 48, t = q % 48;
        if (e0 + e < E) {
            float v[4];
#pragma unroll
            for (int i = 0; i < 4; i++) {
                int idx = t * 4 + i, c = idx / 3, m = idx - c * 3;
                v[i] = Ss[e * 64 + c] * bufB[e * 64 + c] * Ys[e * 8 + m] * SC;
            }
            red_add_v4(&g_agg[(size_t)Rc[e] * AGGW + 64 + t * 4], v[0], v[1], v[2], v[3]);
        }
    }
    __syncthreads();

    // ---- l = 2 : (c,5) block, 80 v4 per edge
    gemm64<false>(bufA, W4 + 128, 192, bufB, 0.125f);
    __syncthreads();
    for (int q = tid; q < 5120; q += 256) {
        int e = q / 80, t = q % 80;
        if (e0 + e < E) {
            float v[4];
#pragma unroll
            for (int i = 0; i < 4; i++) {
                int idx = t * 4 + i, c = idx / 5, m = idx - c * 5;
                v[i] = Ss[e * 64 + c] * bufB[e * 64 + c] * Ys[e * 8 + 3 + m] * SC;
            }
            red_add_v4(&g_agg[(size_t)Rc[e] * AGGW + 256 + t * 4], v[0], v[1], v[2], v[3]);
        }
    }
}

// ---------------------------------------------------------------- down-projection
// out[n][j<64]        = sum_c agg[n][c]          * W0[c][j]          * EPS/sqrt(C)
// out[n][64+d*3+m]    = sum_c agg[n][64+c*3+m]   * W1[c][d]          * EPS/sqrt(C)
// out[n][256+d*5+m]   = sum_c agg[n][256+c*5+m]  * W2[c][d]          * EPS/sqrt(C)
__global__ __launch_bounds__(576, 1) void down_kernel(
    const float* __restrict__ w0, const float* __restrict__ w1,
    const float* __restrict__ w2, float* __restrict__ out, int Nn) {
    extern __shared__ float sm[];
    float* W0 = sm;
    float* W1 = W0 + 4096;
    float* W2 = W1 + 4096;
    float* A  = W2 + 4096;  // 576
    int tid = threadIdx.x;
    for (int i = tid; i < 1024; i += 576) reinterpret_cast<float4*>(W0)[i] = reinterpret_cast<const float4*>(w0)[i];
    for (int i = tid; i < 1024; i += 576) reinterpret_cast<float4*>(W1)[i] = reinterpret_cast<const float4*>(w1)[i];
    for (int i = tid; i < 1024; i += 576) reinterpret_cast<float4*>(W2)[i] = reinterpret_cast<const float4*>(w2)[i];

    const float* Wp;
    int aoff, astr, d;
    if (tid < 64)       { Wp = W0; d = tid;                       aoff = 0;                 astr = 1; }
    else if (tid < 256) { int jj = tid - 64;  d = jj / 3; Wp = W1; aoff = 64  + (jj - d*3); astr = 3; }
    else                { int jj = tid - 256; d = jj / 5; Wp = W2; aoff = 256 + (jj - d*5); astr = 5; }

    int n0 = blockIdx.x * 16;
    for (int it = 0; it < 16; it++) {
        int n = n0 + it;
        if (n >= Nn) break;
        __syncthreads();
        A[tid] = g_agg[(size_t)n * AGGW + tid];
        __syncthreads();
        float acc = 0.f;
#pragma unroll 8
        for (int c = 0; c < 64; c++) acc += A[aoff + c * astr] * Wp[c * 64 + d];
        out[(size_t)n * AGGW + tid] = acc * 0.0625f;  // EPS * (1/sqrt(C)) = 0.5 * 0.125
    }
}

// ---------------------------------------------------------------- launch
extern "C" void kernel_launch(void* const* d_in, const int* in_sizes, int n_in,
                              void* d_out, int out_size) {
    const float* vectors    = (const float*)d_in[0];
    const float* node_feats = (const float*)d_in[1];
    const float* radial     = (const float*)d_in[2];
    const int*   senders    = (const int*)d_in[3];
    const int*   receivers  = (const int*)d_in[4];
    const float* w_up       = (const float*)d_in[5];
    const float* mlp_w1     = (const float*)d_in[6];
    const float* mlp_w2     = (const float*)d_in[7];
    const float* mlp_w3     = (const float*)d_in[8];
    const float* mlp_w4     = (const float*)d_in[9];
    const float* w_down0    = (const float*)d_in[10];
    const float* w_down1    = (const float*)d_in[11];
    const float* w_down2    = (const float*)d_in[12];

    int E = in_sizes[0] / 3;
    int N = in_sizes[1] / CDIM;

    const int EDGE_SMEM = (512 + 4096 + 4096 + 12288 + 4096 + 4096 + 4096 + 512 + 512) * 4 + 128 * 4;
    const int DOWN_SMEM = (4096 * 3 + 576) * 4;
    cudaFuncSetAttribute(edge_kernel, cudaFuncAttributeMaxDynamicSharedMemorySize, EDGE_SMEM);
    cudaFuncSetAttribute(down_kernel, cudaFuncAttributeMaxDynamicSharedMemorySize, DOWN_SMEM);

    zero_agg_kernel<<<2048, 256>>>(N * AGGW / 4);
    h_kernel<<<(N + 3) / 4, 256>>>(node_feats, w_up, N);
    edge_kernel<<<(E + 63) / 64, 256, EDGE_SMEM>>>(vectors, radial, senders, receivers,
                                                   mlp_w1, mlp_w2, mlp_w3, mlp_w4, E);
    down_kernel<<<(N + 15) / 16, 576, DOWN_SMEM>>>(w_down0, w_down1, w_down2, (float*)d_out, N);
}

// round 16
// speedup vs baseline: 1.0418x; 1.0418x over previous
#include <cuda_runtime.h>
#include <cstdint>

#define CDIM 64
#define MAXN 20000
#define AGGW 576   // 64 + 64*3 + 64*5
#define ETILE 128  // edges per tile in edge kernel

// Scratch: __device__ globals (no allocation allowed anywhere).
// __align__(16) is load-bearing: red.global.add.v4.f32 requires 16B-aligned addresses.
__device__ __align__(16) float g_h[MAXN * CDIM];       // up-projected node feats, 5 MB
__device__ __align__(16) float g_agg[MAXN * AGGW];     // scatter accumulator, 46 MB (L2-resident)

__device__ __forceinline__ float silu_f(float x) {
    return x / (1.0f + __expf(-x));
}

__device__ __forceinline__ void red_add_v4(float* addr, float a, float b, float c, float d) {
    asm volatile("red.global.add.v4.f32 [%0], {%1,%2,%3,%4};"
                 :: "l"(addr), "f"(a), "f"(b), "f"(c), "f"(d) : "memory");
}

// ---------------------------------------------------------------- zero agg
__global__ void zero_agg_kernel(int n4) {
    float4 z = make_float4(0.f, 0.f, 0.f, 0.f);
    float4* p = reinterpret_cast<float4*>(g_agg);
    for (int i = blockIdx.x * blockDim.x + threadIdx.x; i < n4; i += gridDim.x * blockDim.x)
        p[i] = z;
}

// ---------------------------------------------------------------- h = nf @ w_up * 1/8
// 16 nodes per block; each thread computes 4 outputs sharing each Ws read.
__global__ __launch_bounds__(256) void h_kernel(const float* __restrict__ nf,
                                                const float* __restrict__ wup, int Nn) {
    __shared__ float Ws[4096];
    __shared__ float nfs[1024];
    const int tid = threadIdx.x;
    for (int i = tid; i < 1024; i += 256)
        reinterpret_cast<float4*>(Ws)[i] = reinterpret_cast<const float4*>(wup)[i];
    const int n0 = blockIdx.x * 16;
    {
        int n = n0 + (tid >> 4);
        float4 v = make_float4(0.f, 0.f, 0.f, 0.f);
        if (n < Nn) v = reinterpret_cast<const float4*>(nf)[(size_t)n * 16 + (tid & 15)];
        reinterpret_cast<float4*>(nfs)[tid] = v;
    }
    __syncthreads();
    const int nl = tid >> 6;     // row group 0..3 -> rows nl*4..nl*4+3
    const int j  = tid & 63;
    float acc0 = 0.f, acc1 = 0.f, acc2 = 0.f, acc3 = 0.f;
    const float* np = nfs + nl * 4 * 64;
#pragma unroll 8
    for (int c = 0; c < 64; c++) {
        float w = Ws[c * 64 + j];
        acc0 += np[c]       * w;
        acc1 += np[64 + c]  * w;
        acc2 += np[128 + c] * w;
        acc3 += np[192 + c] * w;
    }
    int n = n0 + nl * 4;
    if (n + 0 < Nn) g_h[(size_t)(n + 0) * 64 + j] = acc0 * 0.125f;
    if (n + 1 < Nn) g_h[(size_t)(n + 1) * 64 + j] = acc1 * 0.125f;
    if (n + 2 < Nn) g_h[(size_t)(n + 2) * 64 + j] = acc2 * 0.125f;
    if (n + 3 < Nn) g_h[(size_t)(n + 3) * 64 + j] = acc3 * 0.125f;
}

// ---------------------------------------------------------------- register-tiled GEMM
// C[r][j] = act( sum_k A[r][k] * B[k*ldb + j] ),  A: [ROWS][64] smem, C: [ROWS][64] smem.
// Scale constants are pre-folded into B. Uses ROWS*16 threads, 4x4 register tile each.
template <int ROWS, bool DOSILU>
__device__ __forceinline__ void gemm_rt(const float* __restrict__ A,
                                        const float* __restrict__ B, int ldb,
                                        float* __restrict__ Cc) {
    int tx = threadIdx.x & 15;   // output col group (j = tx*4 .. +3)
    int ty = threadIdx.x >> 4;   // output row group (r = ty*4 .. +3), 0..ROWS/4-1
    float acc[4][4];
#pragma unroll
    for (int i = 0; i < 4; i++)
#pragma unroll
        for (int j = 0; j < 4; j++) acc[i][j] = 0.f;
    const float* Bp = B + tx * 4;
    const float* Ap = A + ty * 4 * 64;
#pragma unroll 4
    for (int k = 0; k < 64; k++) {
        float4 b = *reinterpret_cast<const float4*>(Bp + k * ldb);
        float a0 = Ap[k];
        float a1 = Ap[64 + k];
        float a2 = Ap[128 + k];
        float a3 = Ap[192 + k];
        acc[0][0] += a0 * b.x; acc[0][1] += a0 * b.y; acc[0][2] += a0 * b.z; acc[0][3] += a0 * b.w;
        acc[1][0] += a1 * b.x; acc[1][1] += a1 * b.y; acc[1][2] += a1 * b.z; acc[1][3] += a1 * b.w;
        acc[2][0] += a2 * b.x; acc[2][1] += a2 * b.y; acc[2][2] += a2 * b.z; acc[2][3] += a2 * b.w;
        acc[3][0] += a3 * b.x; acc[3][1] += a3 * b.y; acc[3][2] += a3 * b.z; acc[3][3] += a3 * b.w;
    }
#pragma unroll
    for (int i = 0; i < 4; i++) {
        float4 o;
        o.x = acc[i][0]; o.y = acc[i][1]; o.z = acc[i][2]; o.w = acc[i][3];
        if (DOSILU) { o.x = silu_f(o.x); o.y = silu_f(o.y); o.z = silu_f(o.z); o.w = silu_f(o.w); }
        *reinterpret_cast<float4*>(Cc + (ty * 4 + i) * 64 + tx * 4) = o;
    }
}

// ---------------------------------------------------------------- fused persistent edge kernel
// Weights loaded ONCE per block (scales pre-folded); block grid-strides over 128-edge tiles.
// Per tile: radial MLP (8->64->64->64->192), spherical harmonics,
// sender gather (SC pre-folded), factorized message scatter (v4 reductions into g_agg).
// Scatter phase: 4 threads per edge, no runtime div/mod, bounds check hoisted.
__global__ __launch_bounds__(512, 1) void edge_kernel(
    const float* __restrict__ vectors, const float* __restrict__ radial,
    const int* __restrict__ senders, const int* __restrict__ receivers,
    const float* __restrict__ w1, const float* __restrict__ w2,
    const float* __restrict__ w3, const float* __restrict__ w4, int E) {
    extern __shared__ float sm[];
    float* W1   = sm;              // 512
    float* W2   = W1 + 512;        // 4096
    float* W3   = W2 + 4096;       // 4096
    float* W4   = W3 + 4096;       // 12288
    float* bufA = W4 + 12288;      // 8192
    float* bufB = bufA + 8192;     // 8192
    float* Ss   = bufB + 8192;     // 8192   gathered sender feats (pre-scaled by 1/64)
    float* Gs   = Ss + 8192;       // 1024   radial
    float* Ys   = Gs + 1024;       // 1024   y1(3)+y2(5) per edge
    int*   Sn   = reinterpret_cast<int*>(Ys + 1024);  // 128
    int*   Rc   = Sn + 128;                           // 128

    const int tid = threadIdx.x;

    // weights loaded once, layer scales folded in
    const float S1 = 0.35355339059327373f;  // 1/sqrt(8)
    const float S8 = 0.125f;                // 1/sqrt(64)
    for (int i = tid; i < 128; i += 512) {
        float4 v = reinterpret_cast<const float4*>(w1)[i];
        v.x *= S1; v.y *= S1; v.z *= S1; v.w *= S1;
        reinterpret_cast<float4*>(W1)[i] = v;
    }
    for (int i = tid; i < 1024; i += 512) {
        float4 v = reinterpret_cast<const float4*>(w2)[i];
        v.x *= S8; v.y *= S8; v.z *= S8; v.w *= S8;
        reinterpret_cast<float4*>(W2)[i] = v;
    }
    for (int i = tid; i < 1024; i += 512) {
        float4 v = reinterpret_cast<const float4*>(w3)[i];
        v.x *= S8; v.y *= S8; v.z *= S8; v.w *= S8;
        reinterpret_cast<float4*>(W3)[i] = v;
    }
    for (int i = tid; i < 3072; i += 512) {
        float4 v = reinterpret_cast<const float4*>(w4)[i];
        v.x *= S8; v.y *= S8; v.z *= S8; v.w *= S8;
        reinterpret_cast<float4*>(W4)[i] = v;
    }
    __syncthreads();

    const int nTiles = (E + ETILE - 1) / ETILE;
    const float SC = 1.0f / 64.0f;
    const int eS = tid >> 2;      // scatter: edge owned by this thread group
    const int lane4 = tid & 3;    // scatter: lane within the 4-thread edge group

    for (int t = blockIdx.x; t < nTiles; t += gridDim.x) {
        const int e0 = t * ETILE;
        const bool eOK = (e0 + eS) < E;   // hoisted scatter bounds check

        // radial embedding
        for (int i = tid; i < 1024; i += 512) {
            int e = e0 + (i >> 3);
            Gs[i] = (e < E) ? radial[(size_t)e * 8 + (i & 7)] : 0.f;
        }
        // per-edge: ids + spherical harmonics
        if (tid < ETILE) {
            int e = e0 + tid;
            int s = 0, r = 0;
            float vx = 1.f, vy = 0.f, vz = 0.f;
            if (e < E) {
                s = senders[e]; r = receivers[e];
                vx = vectors[(size_t)e * 3 + 0];
                vy = vectors[(size_t)e * 3 + 1];
                vz = vectors[(size_t)e * 3 + 2];
            }
            Sn[tid] = s; Rc[tid] = r;
            float rn = rsqrtf(vx * vx + vy * vy + vz * vz);
            float x = vx * rn, y = vy * rn, z = vz * rn;
            const float s3  = 1.7320508075688772f;   // sqrt(3)
            const float s15 = 3.872983346207417f;    // sqrt(15)
            const float s5h = 1.118033988749895f;    // 0.5*sqrt(5)
            Ys[tid * 8 + 0] = s3 * x;
            Ys[tid * 8 + 1] = s3 * y;
            Ys[tid * 8 + 2] = s3 * z;
            Ys[tid * 8 + 3] = s15 * x * y;
            Ys[tid * 8 + 4] = s15 * y * z;
            Ys[tid * 8 + 5] = s5h * (3.f * z * z - 1.f);
            Ys[tid * 8 + 6] = s15 * x * z;
            Ys[tid * 8 + 7] = 0.5f * s15 * (x * x - y * y);
        }
        __syncthreads();

        // gather sender up-projected feats (g_h fits in L2), pre-fold SC
        for (int i = tid; i < 8192; i += 512)
            Ss[i] = g_h[(size_t)Sn[i >> 6] * 64 + (i & 63)] * SC;

        // MLP layer 1: 8 -> 64 (scale folded into W1)
        for (int i = tid; i < 8192; i += 512) {
            int e = i >> 6, k = i & 63;
            float acc = 0.f;
#pragma unroll
            for (int r8 = 0; r8 < 8; r8++) acc += Gs[e * 8 + r8] * W1[r8 * 64 + k];
            bufA[i] = silu_f(acc);
        }
        __syncthreads();
        gemm_rt<ETILE, true>(bufA, W2, 64, bufB);
        __syncthreads();
        gemm_rt<ETILE, true>(bufB, W3, 64, bufA);  // H3 in bufA
        __syncthreads();

        // ---- l = 0 : mix chunk + scatter (4 v4 per thread)
        gemm_rt<ETILE, false>(bufA, W4, 192, bufB);
        __syncthreads();
        if (eOK) {
            const float* mp = bufB + eS * 64;
            const float* sp = Ss + eS * 64;
            float* ap = &g_agg[(size_t)Rc[eS] * AGGW];
#pragma unroll
            for (int k = 0; k < 4; k++) {
                int c4 = (lane4 + k * 4) * 4;
                red_add_v4(ap + c4,
                           mp[c4] * sp[c4], mp[c4 + 1] * sp[c4 + 1],
                           mp[c4 + 2] * sp[c4 + 2], mp[c4 + 3] * sp[c4 + 3]);
            }
        }
        __syncthreads();

        // ---- l = 1 : (c,3) block, 12 v4 per thread
        gemm_rt<ETILE, false>(bufA, W4 + 64, 192, bufB);
        __syncthreads();
        if (eOK) {
            const float* sp = Ss + eS * 64;
            const float* mp = bufB + eS * 64;
            const float* yp = Ys + eS * 8;
            float* ap = &g_agg[(size_t)Rc[eS] * AGGW + 64];
#pragma unroll
            for (int k = 0; k < 12; k++) {
                int tt = lane4 + k * 4;
                float v[4];
#pragma unroll
                for (int i = 0; i < 4; i++) {
                    int idx = tt * 4 + i, c = idx / 3, m = idx - c * 3;   // const-div
                    v[i] = sp[c] * mp[c] * yp[m];
                }
                red_add_v4(ap + tt * 4, v[0], v[1], v[2], v[3]);
            }
        }
        __syncthreads();

        // ---- l = 2 : (c,5) block, 20 v4 per thread
        gemm_rt<ETILE, false>(bufA, W4 + 128, 192, bufB);
        __syncthreads();
        if (eOK) {
            const float* sp = Ss + eS * 64;
            const float* mp = bufB + eS * 64;
            const float* yp = Ys + eS * 8 + 3;
            float* ap = &g_agg[(size_t)Rc[eS] * AGGW + 256];
#pragma unroll
            for (int k = 0; k < 20; k++) {
                int tt = lane4 + k * 4;
                float v[4];
#pragma unroll
                for (int i = 0; i < 4; i++) {
                    int idx = tt * 4 + i, c = idx / 5, m = idx - c * 5;   // const-div
                    v[i] = sp[c] * mp[c] * yp[m];
                }
                red_add_v4(ap + tt * 4, v[0], v[1], v[2], v[3]);
            }
        }
        __syncthreads();  // protect smem buffers before next tile overwrites
    }
}

// ---------------------------------------------------------------- down-projection as 9 GEMMs
// Per 64-node tile (256 threads):
//   o0[n][j]        = (A0 @ W0)[n][j],       A0[n][c] = agg[n][c]
//   o1[n][d*3+m]    = (A1m @ W1)[n][d],      A1m[n][c] = agg[n][64 + c*3 + m],  m=0..2
//   o2[n][d*5+m]    = (A2m @ W2)[n][d],      A2m[n][c] = agg[n][256 + c*5 + m], m=0..4
// EPS*inv_sqrt_c folded into weights at load. Results written straight from registers.
__global__ __launch_bounds__(256, 2) void down_kernel(
    const float* __restrict__ w0, const float* __restrict__ w1,
    const float* __restrict__ w2, float* __restrict__ out, int Nn) {
    extern __shared__ float sm[];
    float* W0 = sm;           // 4096
    float* W1 = W0 + 4096;    // 4096
    float* W2 = W1 + 4096;    // 4096
    float* Ab = W2 + 4096;    // 4096  A tile [64][64]
    const int tid = threadIdx.x;
    const float SC = 0.0625f;  // EPS * inv_sqrt_c = 0.5 * 0.125
    for (int i = tid; i < 1024; i += 256) {
        float4 v = reinterpret_cast<const float4*>(w0)[i];
        v.x *= SC; v.y *= SC; v.z *= SC; v.w *= SC;
        reinterpret_cast<float4*>(W0)[i] = v;
    }
    for (int i = tid; i < 1024; i += 256) {
        float4 v = reinterpret_cast<const float4*>(w1)[i];
        v.x *= SC; v.y *= SC; v.z *= SC; v.w *= SC;
        reinterpret_cast<float4*>(W1)[i] = v;
    }
    for (int i = tid; i < 1024; i += 256) {
        float4 v = reinterpret_cast<const float4*>(w2)[i];
        v.x *= SC; v.y *= SC; v.z *= SC; v.w *= SC;
        reinterpret_cast<float4*>(W2)[i] = v;
    }

    const int n0 = blockIdx.x * 64;
    const int tx = tid & 15;   // d group (d = tx*4 .. +3)
    const int ty = tid >> 4;   // node group (n = n0 + ty*4 .. +3)

    auto run_gemm = [&](const float* __restrict__ W, int aoff, int astr,
                        int ooff, int ostr) {
        // gather A tile: A[n][c] = agg[n][aoff + c*astr]
        for (int i = tid; i < 4096; i += 256) {
            int n = n0 + (i >> 6), c = i & 63;
            Ab[i] = (n < Nn) ? g_agg[(size_t)n * AGGW + aoff + c * astr] : 0.f;
        }
        __syncthreads();
        float acc[4][4];
#pragma unroll
        for (int i = 0; i < 4; i++)
#pragma unroll
            for (int j = 0; j < 4; j++) acc[i][j] = 0.f;
        const float* Bp = W + tx * 4;
        const float* Ap = Ab + ty * 4 * 64;
#pragma unroll 4
        for (int k = 0; k < 64; k++) {
            float4 b = *reinterpret_cast<const float4*>(Bp + k * 64);
            float a0 = Ap[k];
            float a1 = Ap[64 + k];
            float a2 = Ap[128 + k];
            float a3 = Ap[192 + k];
            acc[0][0] += a0 * b.x; acc[0][1] += a0 * b.y; acc[0][2] += a0 * b.z; acc[0][3] += a0 * b.w;
            acc[1][0] += a1 * b.x; acc[1][1] += a1 * b.y; acc[1][2] += a1 * b.z; acc[1][3] += a1 * b.w;
            acc[2][0] += a2 * b.x; acc[2][1] += a2 * b.y; acc[2][2] += a2 * b.z; acc[2][3] += a2 * b.w;
            acc[3][0] += a3 * b.x; acc[3][1] += a3 * b.y; acc[3][2] += a3 * b.z; acc[3][3] += a3 * b.w;
        }
#pragma unroll
        for (int i = 0; i < 4; i++) {
            int n = n0 + ty * 4 + i;
            if (n < Nn) {
                float* op = out + (size_t)n * AGGW + ooff;
#pragma unroll
                for (int j = 0; j < 4; j++)
                    op[(tx * 4 + j) * ostr] = acc[i][j];
            }
        }
        __syncthreads();  // before next gather overwrites Ab
    };

    run_gemm(W0, 0, 1, 0, 1);                                          // l=0
#pragma unroll
    for (int m = 0; m < 3; m++) run_gemm(W1, 64 + m, 3, 64 + m, 3);    // l=1
#pragma unroll
    for (int m = 0; m < 5; m++) run_gemm(W2, 256 + m, 5, 256 + m, 5);  // l=2
}

// ---------------------------------------------------------------- launch
extern "C" void kernel_launch(void* const* d_in, const int* in_sizes, int n_in,
                              void* d_out, int out_size) {
    const float* vectors    = (const float*)d_in[0];
    const float* node_feats = (const float*)d_in[1];
    const float* radial     = (const float*)d_in[2];
    const int*   senders    = (const int*)d_in[3];
    const int*   receivers  = (const int*)d_in[4];
    const float* w_up       = (const float*)d_in[5];
    const float* mlp_w1     = (const float*)d_in[6];
    const float* mlp_w2     = (const float*)d_in[7];
    const float* mlp_w3     = (const float*)d_in[8];
    const float* mlp_w4     = (const float*)d_in[9];
    const float* w_down0    = (const float*)d_in[10];
    const float* w_down1    = (const float*)d_in[11];
    const float* w_down2    = (const float*)d_in[12];

    int E = in_sizes[0] / 3;
    int N = in_sizes[1] / CDIM;

    const int EDGE_SMEM = (512 + 4096 + 4096 + 12288 + 8192 + 8192 + 8192 + 1024 + 1024) * 4 + 256 * 4;
    const int DOWN_SMEM = (4096 * 4) * 4;
    cudaFuncSetAttribute(edge_kernel, cudaFuncAttributeMaxDynamicSharedMemorySize, EDGE_SMEM);
    cudaFuncSetAttribute(down_kernel, cudaFuncAttributeMaxDynamicSharedMemorySize, DOWN_SMEM);

    zero_agg_kernel<<<2048, 256>>>(N * AGGW / 4);
    h_kernel<<<(N + 15) / 16, 256>>>(node_feats, w_up, N);
    edge_kernel<<<152, 512, EDGE_SMEM>>>(vectors, radial, senders, receivers,
                                         mlp_w1, mlp_w2, mlp_w3, mlp_w4, E);
    down_kernel<<<(N + 63) / 64, 256, DOWN_SMEM>>>(w_down0, w_down1, w_down2, (float*)d_out, N);
}